// round 3
// baseline (speedup 1.0000x reference)
#include <cuda_runtime.h>
#include <cstdint>

// ---------------------------------------------------------------------------
// SimpleRNN: logits = W_out( scan_tanh( W_ih·emb[x] + b_ih , W_hh, b_hh ) ) + b_out
// B=8, S=2048, E=256, H=512, V=16000
// ---------------------------------------------------------------------------

#define B_  8
#define S_  2048
#define E_  256
#define H_  512
#define V_  16000
#define MTOT (B_ * S_)                      // 16384
static const long long VOUT = (long long)B_ * S_ * V_;   // 262,144,000

// Scratch (device globals: no allocation allowed)
__device__ float g_xproj[(size_t)MTOT * H_];   // 33.5 MB
__device__ float g_hseq [(size_t)MTOT * H_];   // 33.5 MB
__device__ float g_dummy_hf[B_ * H_];

// ---------------- packed f32x2 helpers --------------------------------------
__device__ __forceinline__ void ffma2(unsigned long long& acc,
                                      unsigned long long a,
                                      unsigned long long b) {
    asm("fma.rn.f32x2 %0, %1, %2, %0;" : "+l"(acc) : "l"(a), "l"(b));
}
__device__ __forceinline__ unsigned long long pack2(float x, float y) {
    unsigned long long r;
    asm("mov.b64 %0, {%1, %2};" : "=l"(r) : "f"(x), "f"(y));
    return r;
}
__device__ __forceinline__ void unpack2(unsigned long long v, float& lo, float& hi) {
    asm("mov.b64 {%0, %1}, %2;" : "=f"(lo), "=f"(hi) : "l"(v));
}
__device__ __forceinline__ uint32_t smem_u32(const void* p) {
    uint32_t a;
    asm("{ .reg .u64 t; cvta.to.shared.u64 t, %1; cvt.u32.u64 %0, t; }"
        : "=r"(a) : "l"(p));
    return a;
}

// ---------------------------------------------------------------------------
// Kernel 1/3: C[m][n] = sum_k Arow(m)[k] * Bmat[n][k] + bias[n]
// Arow(m) = GATHER ? A + idx[m]*K : A + m*K      (both operands K-minor)
// 128x128 CTA tile, 256 threads, 8x8 microtile, packed f32x2 FMAs,
// double-buffered SMEM. Requires M%128==0, N%128==0, K%8==0 (true here).
// ---------------------------------------------------------------------------
template <bool GATHER>
__global__ __launch_bounds__(256, 2)
void gemm_nt(const float* __restrict__ A, const float* __restrict__ Bmat,
             const float* __restrict__ bias, float* __restrict__ C,
             const int* __restrict__ idx, int M, int N, int K)
{
    __shared__ float As[2][8][128];
    __shared__ float Bs[2][8][128];

    const int tid  = threadIdx.x;
    const int mblk = blockIdx.y * 128;
    const int nblk = blockIdx.x * 128;

    const int arow = tid >> 1;          // 0..127
    const int kq   = (tid & 1) * 4;     // 0 or 4

    const float* Aptr;
    if (GATHER) Aptr = A + (size_t)idx[mblk + arow] * K;
    else        Aptr = A + (size_t)(mblk + arow) * K;
    const float* Bptr = Bmat + (size_t)(nblk + arow) * K;

    const int ty = tid >> 4;            // 0..15 : row group
    const int tx = tid & 15;            // 0..15 : col group

    unsigned long long acc2[8][4];
    #pragma unroll
    for (int i = 0; i < 8; i++)
        #pragma unroll
        for (int p = 0; p < 4; p++) acc2[i][p] = 0ull;

    // prologue: tile 0
    {
        float4 a4 = *(const float4*)(Aptr + kq);
        float4 b4 = *(const float4*)(Bptr + kq);
        #pragma unroll
        for (int i = 0; i < 4; i++) {
            As[0][kq + i][arow] = ((const float*)&a4)[i];
            Bs[0][kq + i][arow] = ((const float*)&b4)[i];
        }
    }
    __syncthreads();

    const int nkt = K >> 3;
    for (int kt = 0; kt < nkt; kt++) {
        const int cur = kt & 1, nxt = cur ^ 1;
        float4 a4n, b4n;
        const bool more = (kt + 1 < nkt);
        if (more) {
            a4n = *(const float4*)(Aptr + (kt + 1) * 8 + kq);
            b4n = *(const float4*)(Bptr + (kt + 1) * 8 + kq);
        }
        #pragma unroll
        for (int k = 0; k < 8; k++) {
            float af[8];
            *(float4*)&af[0] = *(const float4*)&As[cur][k][ty * 8];
            *(float4*)&af[4] = *(const float4*)&As[cur][k][ty * 8 + 4];
            unsigned long long bp[4];
            const unsigned long long* bq =
                (const unsigned long long*)&Bs[cur][k][tx * 8];
            #pragma unroll
            for (int p = 0; p < 4; p++) bp[p] = bq[p];
            #pragma unroll
            for (int i = 0; i < 8; i++) {
                unsigned long long ad = pack2(af[i], af[i]);
                #pragma unroll
                for (int p = 0; p < 4; p++) ffma2(acc2[i][p], ad, bp[p]);
            }
        }
        if (more) {
            #pragma unroll
            for (int i = 0; i < 4; i++) {
                As[nxt][kq + i][arow] = ((const float*)&a4n)[i];
                Bs[nxt][kq + i][arow] = ((const float*)&b4n)[i];
            }
        }
        __syncthreads();
    }

    // epilogue: + bias, store
    float bv[8];
    #pragma unroll
    for (int j = 0; j < 8; j++) bv[j] = bias[nblk + tx * 8 + j];

    #pragma unroll
    for (int i = 0; i < 8; i++) {
        size_t row = (size_t)(mblk + ty * 8 + i);
        float* cp = C + row * (size_t)N + nblk + tx * 8;
        float v[8];
        #pragma unroll
        for (int p = 0; p < 4; p++) {
            float lo, hi;
            unpack2(acc2[i][p], lo, hi);
            v[2 * p]     = lo + bv[2 * p];
            v[2 * p + 1] = hi + bv[2 * p + 1];
        }
        *(float4*)cp       = make_float4(v[0], v[1], v[2], v[3]);
        *(float4*)(cp + 4) = make_float4(v[4], v[5], v[6], v[7]);
    }
}

// ---------------------------------------------------------------------------
// Kernel 2: RNN scan. 8 clusters (one per batch) x 8 CTAs x 512 threads.
// Each CTA owns 64 h-dims; W_hh slice lives in registers (32 f32x2/thread).
// h double-buffered in SMEM, broadcast to the 8 cluster CTAs via mapa +
// st.shared::cluster; one barrier.cluster per timestep.
//   thread tid: out = tid&63 (h-dim within slice), kc = tid>>6 (k-chunk of 64)
// ---------------------------------------------------------------------------
__global__ __launch_bounds__(512, 1) __cluster_dims__(8, 1, 1)
void rnn_scan(const float* __restrict__ xproj,
              const float* __restrict__ hidden0,
              const float* __restrict__ W_hh,
              const float* __restrict__ b_hh,
              float* __restrict__ hseq,
              float* __restrict__ hfinal)
{
    __shared__ float h_buf[2][H_];
    __shared__ float part[8][64];

    const int tid   = threadIdx.x;
    const int batch = blockIdx.x >> 3;
    const int rank  = blockIdx.x & 7;
    const int out   = tid & 63;
    const int kc    = tid >> 6;          // 0..7
    const int kbase = kc * 64;
    const int grow  = rank * 64 + out;   // global h row produced

    // W_hh slice -> registers as packed pairs (64 regs)
    unsigned long long w2[32];
    {
        const unsigned long long* wq =
            (const unsigned long long*)(W_hh + (size_t)grow * H_ + kbase);
        #pragma unroll
        for (int j = 0; j < 32; j++) w2[j] = wq[j];
    }

    h_buf[0][tid] = hidden0[batch * H_ + tid];
    const float bhh = (tid < 64) ? b_hh[rank * 64 + tid] : 0.f;
    __syncthreads();

    const float* xp_b = xproj + (size_t)batch * S_ * H_ + rank * 64;
    float*       hs_b = hseq  + (size_t)batch * S_ * H_ + rank * 64;

    float hn = 0.f;
    for (int t = 0; t < S_; t++) {
        const int pb = t & 1;

        // early LDG: x_proj for this step (consumed after the FMA phase)
        float xp = 0.f;
        if (tid < 64) xp = xp_b[(size_t)t * H_ + tid];

        // partial dot: 64 k-values via 32 packed FMAs (h loads broadcast)
        unsigned long long acc2 = 0ull;
        const unsigned long long* hq =
            (const unsigned long long*)&h_buf[pb][kbase];
        #pragma unroll
        for (int j = 0; j < 32; j++) ffma2(acc2, w2[j], hq[j]);
        float lo, hi; unpack2(acc2, lo, hi);
        part[kc][out] = lo + hi;
        __syncthreads();

        if (tid < 64) {
            float s = xp + bhh;
            #pragma unroll
            for (int c = 0; c < 8; c++) s += part[c][tid];
            hn = tanhf(s);
            hs_b[(size_t)t * H_ + tid] = hn;

            // broadcast into every cluster CTA's other h buffer (incl. self)
            uint32_t laddr = smem_u32(&h_buf[pb ^ 1][rank * 64 + tid]);
            #pragma unroll
            for (int pr = 0; pr < 8; pr++) {
                uint32_t paddr;
                asm("mapa.shared::cluster.u32 %0, %1, %2;"
                    : "=r"(paddr) : "r"(laddr), "r"(pr));
                asm volatile("st.shared::cluster.f32 [%0], %1;"
                             :: "r"(paddr), "f"(hn) : "memory");
            }
        }
        // one cluster barrier per step (arrive=release, wait=acquire)
        asm volatile("barrier.cluster.arrive.aligned;" ::: "memory");
        asm volatile("barrier.cluster.wait.aligned;"   ::: "memory");
    }

    if (tid < 64) hfinal[batch * H_ + rank * 64 + tid] = hn;
}

// ---------------------------------------------------------------------------
// Launch
// inputs: 0=x(i32)[B,S] 1=hidden[B,H] 2=embedding[V,E] 3=W_ih[H,E]
//         4=W_hh[H,H] 5=b_ih[H] 6=b_hh[H] 7=W_out[V,H] 8=b_out[V]
// output: logits [B,S,V] then h_final [B,H]
// ---------------------------------------------------------------------------
extern "C" void kernel_launch(void* const* d_in, const int* in_sizes, int n_in,
                              void* d_out, int out_size)
{
    const int*   x         = (const int*)  d_in[0];
    const float* hidden    = (const float*)d_in[1];
    const float* embedding = (const float*)d_in[2];
    const float* W_ih      = (const float*)d_in[3];
    const float* W_hh      = (const float*)d_in[4];
    const float* b_ih      = (const float*)d_in[5];
    const float* b_hh      = (const float*)d_in[6];
    const float* W_out     = (const float*)d_in[7];
    const float* b_out     = (const float*)d_in[8];
    float* out = (float*)d_out;

    float *xproj, *hseq, *dummy;
    cudaGetSymbolAddress((void**)&xproj, g_xproj);
    cudaGetSymbolAddress((void**)&hseq,  g_hseq);
    cudaGetSymbolAddress((void**)&dummy, g_dummy_hf);

    float* hfin = ((long long)out_size >= VOUT + (long long)B_ * H_)
                      ? (out + VOUT) : dummy;

    // 1) x_proj = emb[x] @ W_ih^T + b_ih     [16384,512]
    gemm_nt<true><<<dim3(H_ / 128, MTOT / 128), 256>>>(
        embedding, W_ih, b_ih, xproj, x, MTOT, H_, E_);

    // 2) sequential scan -> hseq, h_final
    rnn_scan<<<64, 512>>>(xproj, hidden, W_hh, b_hh, hseq, hfin);

    // 3) logits = hseq @ W_out^T + b_out    [16384,16000]
    gemm_nt<false><<<dim3(V_ / 128, MTOT / 128), 256>>>(
        hseq, W_out, b_out, out, nullptr, MTOT, V_, H_);
}

// round 5
// speedup vs baseline: 1.8599x; 1.8599x over previous
#include <cuda_runtime.h>
#include <cuda_bf16.h>
#include <cstdint>

// ---------------------------------------------------------------------------
// SimpleRNN: logits = W_out( scan_tanh( W_ih·emb[x] + b_ih , W_hh, b_hh ) ) + b_out
// B=8, S=2048, E=256, H=512, V=16000
// Round 4: logits GEMM via mma.sync bf16 (arch-neutral tensor path; the
// harness's ptxas rejects tcgen05 on the non-'a' compute_103 target).
// fp32 accuracy via bf16 3-term split accumulated in fp32.
// ---------------------------------------------------------------------------

#define B_  8
#define S_  2048
#define E_  256
#define H_  512
#define V_  16000
#define MTOT (B_ * S_)                      // 16384
static const long long VOUT = (long long)B_ * S_ * V_;   // 262,144,000

// Scratch (device globals: no allocation allowed)
__device__ float          g_xproj[(size_t)MTOT * H_];    // 33.5 MB
__device__ __nv_bfloat16  g_hhi  [(size_t)MTOT * H_];    // 16.8 MB
__device__ __nv_bfloat16  g_hlo  [(size_t)MTOT * H_];    // 16.8 MB
__device__ __nv_bfloat16  g_whi  [(size_t)V_  * H_];     // 16.4 MB
__device__ __nv_bfloat16  g_wlo  [(size_t)V_  * H_];     // 16.4 MB
__device__ float          g_dummy_hf[B_ * H_];

// ---------------- small PTX helpers -----------------------------------------
__device__ __forceinline__ void ffma2(unsigned long long& acc,
                                      unsigned long long a,
                                      unsigned long long b) {
    asm("fma.rn.f32x2 %0, %1, %2, %0;" : "+l"(acc) : "l"(a), "l"(b));
}
__device__ __forceinline__ unsigned long long pack2(float x, float y) {
    unsigned long long r;
    asm("mov.b64 %0, {%1, %2};" : "=l"(r) : "f"(x), "f"(y));
    return r;
}
__device__ __forceinline__ void unpack2(unsigned long long v, float& lo, float& hi) {
    asm("mov.b64 {%0, %1}, %2;" : "=f"(lo), "=f"(hi) : "l"(v));
}
__device__ __forceinline__ uint32_t smem_u32(const void* p) {
    uint32_t a;
    asm("{ .reg .u64 t; cvta.to.shared.u64 t, %1; cvt.u32.u64 %0, t; }"
        : "=r"(a) : "l"(p));
    return a;
}
__device__ __forceinline__ void cp_async16(uint32_t saddr, const void* gaddr) {
    asm volatile("cp.async.cg.shared.global [%0], [%1], 16;"
                 :: "r"(saddr), "l"(gaddr));
}
#define CP_COMMIT() asm volatile("cp.async.commit_group;" ::: "memory")
template <int N>
__device__ __forceinline__ void cp_wait() {
    asm volatile("cp.async.wait_group %0;" :: "n"(N) : "memory");
}
__device__ __forceinline__ void ldsm4(uint32_t addr, uint32_t& r0, uint32_t& r1,
                                      uint32_t& r2, uint32_t& r3) {
    asm volatile("ldmatrix.sync.aligned.m8n8.x4.shared.b16 {%0,%1,%2,%3}, [%4];"
                 : "=r"(r0), "=r"(r1), "=r"(r2), "=r"(r3) : "r"(addr));
}
__device__ __forceinline__ void mma_bf16(float* d,
                                         uint32_t a0, uint32_t a1,
                                         uint32_t a2, uint32_t a3,
                                         uint32_t b0, uint32_t b1) {
    asm volatile("mma.sync.aligned.m16n8k16.row.col.f32.bf16.bf16.f32 "
                 "{%0,%1,%2,%3}, {%4,%5,%6,%7}, {%8,%9}, {%0,%1,%2,%3};"
                 : "+f"(d[0]), "+f"(d[1]), "+f"(d[2]), "+f"(d[3])
                 : "r"(a0), "r"(a1), "r"(a2), "r"(a3), "r"(b0), "r"(b1));
}

// ---------------------------------------------------------------------------
// Kernel 0: split fp32 -> (bf16 hi, bf16 lo)
// ---------------------------------------------------------------------------
__global__ void split_f32(const float* __restrict__ src,
                          __nv_bfloat16* __restrict__ hi,
                          __nv_bfloat16* __restrict__ lo, int n)
{
    int i = blockIdx.x * blockDim.x + threadIdx.x;
    int stride = gridDim.x * blockDim.x;
    for (; i < n; i += stride) {
        float v = src[i];
        __nv_bfloat16 h = __float2bfloat16(v);
        hi[i] = h;
        lo[i] = __float2bfloat16(v - __bfloat162float(h));
    }
}

// ---------------------------------------------------------------------------
// Kernel 1: x_proj SGEMM (123us, unchanged)
// ---------------------------------------------------------------------------
template <bool GATHER>
__global__ __launch_bounds__(256, 2)
void gemm_nt(const float* __restrict__ A, const float* __restrict__ Bmat,
             const float* __restrict__ bias, float* __restrict__ C,
             const int* __restrict__ idx, int M, int N, int K)
{
    __shared__ float As[2][8][128];
    __shared__ float Bs[2][8][128];

    const int tid  = threadIdx.x;
    const int mblk = blockIdx.y * 128;
    const int nblk = blockIdx.x * 128;

    const int arow = tid >> 1;
    const int kq   = (tid & 1) * 4;

    const float* Aptr;
    if (GATHER) Aptr = A + (size_t)idx[mblk + arow] * K;
    else        Aptr = A + (size_t)(mblk + arow) * K;
    const float* Bptr = Bmat + (size_t)(nblk + arow) * K;

    const int ty = tid >> 4;
    const int tx = tid & 15;

    unsigned long long acc2[8][4];
    #pragma unroll
    for (int i = 0; i < 8; i++)
        #pragma unroll
        for (int p = 0; p < 4; p++) acc2[i][p] = 0ull;

    {
        float4 a4 = *(const float4*)(Aptr + kq);
        float4 b4 = *(const float4*)(Bptr + kq);
        #pragma unroll
        for (int i = 0; i < 4; i++) {
            As[0][kq + i][arow] = ((const float*)&a4)[i];
            Bs[0][kq + i][arow] = ((const float*)&b4)[i];
        }
    }
    __syncthreads();

    const int nkt = K >> 3;
    for (int kt = 0; kt < nkt; kt++) {
        const int cur = kt & 1, nxt = cur ^ 1;
        float4 a4n, b4n;
        const bool more = (kt + 1 < nkt);
        if (more) {
            a4n = *(const float4*)(Aptr + (kt + 1) * 8 + kq);
            b4n = *(const float4*)(Bptr + (kt + 1) * 8 + kq);
        }
        #pragma unroll
        for (int k = 0; k < 8; k++) {
            float af[8];
            *(float4*)&af[0] = *(const float4*)&As[cur][k][ty * 8];
            *(float4*)&af[4] = *(const float4*)&As[cur][k][ty * 8 + 4];
            unsigned long long bp[4];
            const unsigned long long* bq =
                (const unsigned long long*)&Bs[cur][k][tx * 8];
            #pragma unroll
            for (int p = 0; p < 4; p++) bp[p] = bq[p];
            #pragma unroll
            for (int i = 0; i < 8; i++) {
                unsigned long long ad = pack2(af[i], af[i]);
                #pragma unroll
                for (int p = 0; p < 4; p++) ffma2(acc2[i][p], ad, bp[p]);
            }
        }
        if (more) {
            #pragma unroll
            for (int i = 0; i < 4; i++) {
                As[nxt][kq + i][arow] = ((const float*)&a4n)[i];
                Bs[nxt][kq + i][arow] = ((const float*)&b4n)[i];
            }
        }
        __syncthreads();
    }

    float bv[8];
    #pragma unroll
    for (int j = 0; j < 8; j++) bv[j] = bias[nblk + tx * 8 + j];

    #pragma unroll
    for (int i = 0; i < 8; i++) {
        size_t row = (size_t)(mblk + ty * 8 + i);
        float* cp = C + row * (size_t)N + nblk + tx * 8;
        float v[8];
        #pragma unroll
        for (int p = 0; p < 4; p++) {
            float lo, hi;
            unpack2(acc2[i][p], lo, hi);
            v[2 * p]     = lo + bv[2 * p];
            v[2 * p + 1] = hi + bv[2 * p + 1];
        }
        *(float4*)cp       = make_float4(v[0], v[1], v[2], v[3]);
        *(float4*)(cp + 4) = make_float4(v[4], v[5], v[6], v[7]);
    }
}

// ---------------------------------------------------------------------------
// Kernel 2: RNN scan (unchanged; emits hseq as bf16 hi/lo)
// ---------------------------------------------------------------------------
__global__ __launch_bounds__(512, 1) __cluster_dims__(8, 1, 1)
void rnn_scan(const float* __restrict__ xproj,
              const float* __restrict__ hidden0,
              const float* __restrict__ W_hh,
              const float* __restrict__ b_hh,
              __nv_bfloat16* __restrict__ hs_hi,
              __nv_bfloat16* __restrict__ hs_lo,
              float* __restrict__ hfinal)
{
    __shared__ float h_buf[2][H_];
    __shared__ float part[8][64];

    const int tid   = threadIdx.x;
    const int batch = blockIdx.x >> 3;
    const int rank  = blockIdx.x & 7;
    const int out   = tid & 63;
    const int kc    = tid >> 6;
    const int kbase = kc * 64;
    const int grow  = rank * 64 + out;

    unsigned long long w2[32];
    {
        const unsigned long long* wq =
            (const unsigned long long*)(W_hh + (size_t)grow * H_ + kbase);
        #pragma unroll
        for (int j = 0; j < 32; j++) w2[j] = wq[j];
    }

    h_buf[0][tid] = hidden0[batch * H_ + tid];
    const float bhh = (tid < 64) ? b_hh[rank * 64 + tid] : 0.f;
    __syncthreads();

    const float* xp_b = xproj + (size_t)batch * S_ * H_ + rank * 64;
    __nv_bfloat16* hh_b = hs_hi + (size_t)batch * S_ * H_ + rank * 64;
    __nv_bfloat16* hl_b = hs_lo + (size_t)batch * S_ * H_ + rank * 64;

    float hn = 0.f;
    for (int t = 0; t < S_; t++) {
        const int pb = t & 1;

        float xp = 0.f;
        if (tid < 64) xp = xp_b[(size_t)t * H_ + tid];

        unsigned long long acc2 = 0ull;
        const unsigned long long* hq =
            (const unsigned long long*)&h_buf[pb][kbase];
        #pragma unroll
        for (int j = 0; j < 32; j++) ffma2(acc2, w2[j], hq[j]);
        float lo, hi; unpack2(acc2, lo, hi);
        part[kc][out] = lo + hi;
        __syncthreads();

        if (tid < 64) {
            float s = xp + bhh;
            #pragma unroll
            for (int c = 0; c < 8; c++) s += part[c][tid];
            hn = tanhf(s);
            __nv_bfloat16 hh = __float2bfloat16(hn);
            hh_b[(size_t)t * H_ + tid] = hh;
            hl_b[(size_t)t * H_ + tid] =
                __float2bfloat16(hn - __bfloat162float(hh));

            uint32_t laddr = smem_u32(&h_buf[pb ^ 1][rank * 64 + tid]);
            #pragma unroll
            for (int pr = 0; pr < 8; pr++) {
                uint32_t paddr;
                asm("mapa.shared::cluster.u32 %0, %1, %2;"
                    : "=r"(paddr) : "r"(laddr), "r"(pr));
                asm volatile("st.shared::cluster.f32 [%0], %1;"
                             :: "r"(paddr), "f"(hn) : "memory");
            }
        }
        asm volatile("barrier.cluster.arrive.aligned;" ::: "memory");
        asm volatile("barrier.cluster.wait.aligned;"   ::: "memory");
    }

    if (tid < 64) hfinal[batch * H_ + rank * 64 + tid] = hn;
}

// ---------------------------------------------------------------------------
// Kernel 3: logits GEMM via mma.sync bf16.
// C[16384,16000] = hseq[16384,512] @ W_out^T + b_out, fp32 via 3-term split:
//   D += Ahi*Bhi + Ahi*Blo + Alo*Bhi  (same fp32 accumulators)
// 128x128 CTA tile, 8 warps (4M x 2N, 32x64 warp tile), K-chunk 64,
// 2-stage cp.async pipeline, 144B-padded SMEM rows (conflict-free ldmatrix).
// ---------------------------------------------------------------------------
#define OP_PITCH  144                       // bytes per smem row (64 bf16 + pad)
#define OP_SZ     (128 * OP_PITCH)          // 18432 B per operand tile
#define STAGE_SZ  (4 * OP_SZ)               // Ahi,Alo,Bhi,Blo
#define LOGITS_SMEM (2 * STAGE_SZ)          // 147456 B

__global__ __launch_bounds__(256, 1)
void logits_mma(const __nv_bfloat16* __restrict__ Ahi,
                const __nv_bfloat16* __restrict__ Alo,
                const __nv_bfloat16* __restrict__ Bhi,
                const __nv_bfloat16* __restrict__ Blo,
                const float* __restrict__ bias,
                float* __restrict__ C)
{
    extern __shared__ char dsm[];
    const uint32_t sbase = smem_u32(dsm);

    const int tid  = threadIdx.x;
    const int warp = tid >> 5, lane = tid & 31;
    const int wm = warp & 3;                 // 0..3  (M)
    const int wn = warp >> 2;                // 0..1  (N)
    const int mblk = blockIdx.y * 128;
    const int nblk = blockIdx.x * 128;

    const char* opg[4] = { (const char*)Ahi, (const char*)Alo,
                           (const char*)Bhi, (const char*)Blo };
    const int   r0op[4] = { mblk, mblk, nblk, nblk };

    // per-thread load pattern: 4 chunks of 16B per operand per stage
    // u = tid + 256*j : row = u>>3 (0..127), chunk col = u&7 (0..7)
    auto load_stage = [&](int kc, int st) {
        const uint32_t sst = sbase + (uint32_t)st * STAGE_SZ;
        #pragma unroll
        for (int op = 0; op < 4; op++) {
            #pragma unroll
            for (int j = 0; j < 4; j++) {
                int u = tid + 256 * j;
                int row = u >> 3, cc = u & 7;
                const void* g = opg[op] +
                    (size_t)(r0op[op] + row) * (H_ * 2) + kc * 128 + cc * 16;
                uint32_t s = sst + (uint32_t)op * OP_SZ + row * OP_PITCH + cc * 16;
                cp_async16(s, g);
            }
        }
        CP_COMMIT();
    };

    float acc[2][8][4];
    #pragma unroll
    for (int mi = 0; mi < 2; mi++)
        #pragma unroll
        for (int ni = 0; ni < 8; ni++)
            #pragma unroll
            for (int q = 0; q < 4; q++) acc[mi][ni][q] = 0.f;

    load_stage(0, 0);
    load_stage(1, 1);

    // ldmatrix address components (bytes within operand tile)
    const int arow  = wm * 32 + (lane & 15);          // + mi*16
    const int aoff  = (lane >> 4) * 16;               // bytes: (lane/16)*8 elems
    const int nrow  = wn * 64 + (lane & 7) + ((lane >> 4) & 1) * 8;  // + g*16
    const int boff  = ((lane >> 3) & 1) * 16;         // bytes

    #pragma unroll 1
    for (int kc = 0; kc < 8; kc++) {
        const int st = kc & 1;
        if (kc < 7) cp_wait<1>(); else cp_wait<0>();
        __syncthreads();

        const uint32_t sst = sbase + (uint32_t)st * STAGE_SZ;
        const uint32_t ahb = sst;
        const uint32_t alb = sst + OP_SZ;
        const uint32_t bhb = sst + 2 * OP_SZ;
        const uint32_t blb = sst + 3 * OP_SZ;

        #pragma unroll
        for (int ks = 0; ks < 4; ks++) {
            const int kb = ks * 32;   // bytes (16 bf16)
            uint32_t ah[2][4], al[2][4];
            #pragma unroll
            for (int mi = 0; mi < 2; mi++) {
                ldsm4(ahb + (arow + mi * 16) * OP_PITCH + kb + aoff,
                      ah[mi][0], ah[mi][1], ah[mi][2], ah[mi][3]);
                ldsm4(alb + (arow + mi * 16) * OP_PITCH + kb + aoff,
                      al[mi][0], al[mi][1], al[mi][2], al[mi][3]);
            }
            #pragma unroll
            for (int g = 0; g < 4; g++) {
                uint32_t bh[4], bl[4];
                ldsm4(bhb + (nrow + g * 16) * OP_PITCH + kb + boff,
                      bh[0], bh[1], bh[2], bh[3]);
                ldsm4(blb + (nrow + g * 16) * OP_PITCH + kb + boff,
                      bl[0], bl[1], bl[2], bl[3]);
                #pragma unroll
                for (int mi = 0; mi < 2; mi++) {
                    float* d0 = acc[mi][2 * g];
                    float* d1 = acc[mi][2 * g + 1];
                    mma_bf16(d0, ah[mi][0], ah[mi][1], ah[mi][2], ah[mi][3],
                             bh[0], bh[1]);
                    mma_bf16(d0, ah[mi][0], ah[mi][1], ah[mi][2], ah[mi][3],
                             bl[0], bl[1]);
                    mma_bf16(d0, al[mi][0], al[mi][1], al[mi][2], al[mi][3],
                             bh[0], bh[1]);
                    mma_bf16(d1, ah[mi][0], ah[mi][1], ah[mi][2], ah[mi][3],
                             bh[2], bh[3]);
                    mma_bf16(d1, ah[mi][0], ah[mi][1], ah[mi][2], ah[mi][3],
                             bl[2], bl[3]);
                    mma_bf16(d1, al[mi][0], al[mi][1], al[mi][2], al[mi][3],
                             bh[2], bh[3]);
                }
            }
        }
        __syncthreads();
        if (kc + 2 < 8) load_stage(kc + 2, st);
    }

    // epilogue: fragment rows = lane/4 (+8), cols = (lane%4)*2
    const int rg = mblk + wm * 32 + (lane >> 2);
    const int cg = nblk + wn * 64 + (lane & 3) * 2;
    #pragma unroll
    for (int mi = 0; mi < 2; mi++) {
        #pragma unroll
        for (int ni = 0; ni < 8; ni++) {
            const int row = rg + mi * 16;
            const int col = cg + ni * 8;
            const float b0 = __ldg(bias + col);
            const float b1 = __ldg(bias + col + 1);
            float2 v0 = make_float2(acc[mi][ni][0] + b0, acc[mi][ni][1] + b1);
            float2 v1 = make_float2(acc[mi][ni][2] + b0, acc[mi][ni][3] + b1);
            *(float2*)(C + (size_t)row * V_ + col)       = v0;
            *(float2*)(C + (size_t)(row + 8) * V_ + col) = v1;
        }
    }
}

// ---------------------------------------------------------------------------
// Launch
// inputs: 0=x(i32)[B,S] 1=hidden[B,H] 2=embedding[V,E] 3=W_ih[H,E]
//         4=W_hh[H,H] 5=b_ih[H] 6=b_hh[H] 7=W_out[V,H] 8=b_out[V]
// output: logits [B,S,V] then h_final [B,H]
// ---------------------------------------------------------------------------
extern "C" void kernel_launch(void* const* d_in, const int* in_sizes, int n_in,
                              void* d_out, int out_size)
{
    const int*   x         = (const int*)  d_in[0];
    const float* hidden    = (const float*)d_in[1];
    const float* embedding = (const float*)d_in[2];
    const float* W_ih      = (const float*)d_in[3];
    const float* W_hh      = (const float*)d_in[4];
    const float* b_ih      = (const float*)d_in[5];
    const float* b_hh      = (const float*)d_in[6];
    const float* W_out     = (const float*)d_in[7];
    const float* b_out     = (const float*)d_in[8];
    float* out = (float*)d_out;

    float *xproj, *dummy;
    __nv_bfloat16 *hhi, *hlo, *whi, *wlo;
    cudaGetSymbolAddress((void**)&xproj, g_xproj);
    cudaGetSymbolAddress((void**)&hhi,   g_hhi);
    cudaGetSymbolAddress((void**)&hlo,   g_hlo);
    cudaGetSymbolAddress((void**)&whi,   g_whi);
    cudaGetSymbolAddress((void**)&wlo,   g_wlo);
    cudaGetSymbolAddress((void**)&dummy, g_dummy_hf);

    float* hfin = ((long long)out_size >= VOUT + (long long)B_ * H_)
                      ? (out + VOUT) : dummy;

    static bool attr_done = false;
    if (!attr_done) {
        cudaFuncSetAttribute(logits_mma,
                             cudaFuncAttributeMaxDynamicSharedMemorySize,
                             LOGITS_SMEM);
        attr_done = true;
    }

    // 0) split W_out -> bf16 hi/lo
    split_f32<<<2048, 256>>>(W_out, whi, wlo, V_ * H_);

    // 1) x_proj = emb[x] @ W_ih^T + b_ih     [16384,512]
    gemm_nt<true><<<dim3(H_ / 128, MTOT / 128), 256>>>(
        embedding, W_ih, b_ih, xproj, x, MTOT, H_, E_);

    // 2) sequential scan -> hseq (bf16 hi/lo), h_final
    rnn_scan<<<64, 512>>>(xproj, hidden, W_hh, b_hh, hhi, hlo, hfin);

    // 3) logits = hseq @ W_out^T + b_out    [16384,16000] via mma.sync
    logits_mma<<<dim3(V_ / 128, MTOT / 128), 256, LOGITS_SMEM>>>(
        hhi, hlo, whi, wlo, b_out, out);
}

// round 6
// speedup vs baseline: 2.3311x; 1.2534x over previous
#include <cuda_runtime.h>
#include <cuda_bf16.h>
#include <cuda_fp16.h>
#include <cstdint>

// ---------------------------------------------------------------------------
// SimpleRNN: logits = W_out( scan_tanh( W_ih·emb[x] + b_ih , W_hh, b_hh ) ) + b_out
// B=8, S=2048, E=256, H=512, V=16000
// Round 5: logits GEMM via mma.sync fp16 2-term split:
//   A = hseq exact as (Ahi + Alo) fp16 pair; B = W_out single fp16.
//   D = Ahi*B + Alo*B  (fp32 accum). Error = B fp16 rounding ~1.4e-4 rel.
// 2 CTAs/SM (smem 110.6KB, regs capped at 128) to fill the tensor pipe.
// ---------------------------------------------------------------------------

#define B_  8
#define S_  2048
#define E_  256
#define H_  512
#define V_  16000
#define MTOT (B_ * S_)                      // 16384
static const long long VOUT = (long long)B_ * S_ * V_;   // 262,144,000

// Scratch (device globals: no allocation allowed)
__device__ float  g_xproj[(size_t)MTOT * H_];    // 33.5 MB
__device__ __half g_hhi  [(size_t)MTOT * H_];    // 16.8 MB
__device__ __half g_hlo  [(size_t)MTOT * H_];    // 16.8 MB
__device__ __half g_w16  [(size_t)V_  * H_];     // 16.4 MB
__device__ float  g_dummy_hf[B_ * H_];

// ---------------- small PTX helpers -----------------------------------------
__device__ __forceinline__ void ffma2(unsigned long long& acc,
                                      unsigned long long a,
                                      unsigned long long b) {
    asm("fma.rn.f32x2 %0, %1, %2, %0;" : "+l"(acc) : "l"(a), "l"(b));
}
__device__ __forceinline__ unsigned long long pack2(float x, float y) {
    unsigned long long r;
    asm("mov.b64 %0, {%1, %2};" : "=l"(r) : "f"(x), "f"(y));
    return r;
}
__device__ __forceinline__ void unpack2(unsigned long long v, float& lo, float& hi) {
    asm("mov.b64 {%0, %1}, %2;" : "=f"(lo), "=f"(hi) : "l"(v));
}
__device__ __forceinline__ uint32_t smem_u32(const void* p) {
    uint32_t a;
    asm("{ .reg .u64 t; cvta.to.shared.u64 t, %1; cvt.u32.u64 %0, t; }"
        : "=r"(a) : "l"(p));
    return a;
}
__device__ __forceinline__ void cp_async16(uint32_t saddr, const void* gaddr) {
    asm volatile("cp.async.cg.shared.global [%0], [%1], 16;"
                 :: "r"(saddr), "l"(gaddr));
}
#define CP_COMMIT() asm volatile("cp.async.commit_group;" ::: "memory")
template <int N>
__device__ __forceinline__ void cp_wait() {
    asm volatile("cp.async.wait_group %0;" :: "n"(N) : "memory");
}
__device__ __forceinline__ void ldsm4(uint32_t addr, uint32_t& r0, uint32_t& r1,
                                      uint32_t& r2, uint32_t& r3) {
    asm volatile("ldmatrix.sync.aligned.m8n8.x4.shared.b16 {%0,%1,%2,%3}, [%4];"
                 : "=r"(r0), "=r"(r1), "=r"(r2), "=r"(r3) : "r"(addr));
}
__device__ __forceinline__ void mma_f16(float* d,
                                        uint32_t a0, uint32_t a1,
                                        uint32_t a2, uint32_t a3,
                                        uint32_t b0, uint32_t b1) {
    asm volatile("mma.sync.aligned.m16n8k16.row.col.f32.f16.f16.f32 "
                 "{%0,%1,%2,%3}, {%4,%5,%6,%7}, {%8,%9}, {%0,%1,%2,%3};"
                 : "+f"(d[0]), "+f"(d[1]), "+f"(d[2]), "+f"(d[3])
                 : "r"(a0), "r"(a1), "r"(a2), "r"(a3), "r"(b0), "r"(b1));
}

// ---------------------------------------------------------------------------
// Kernel 0: W_out fp32 -> fp16 (single)
// ---------------------------------------------------------------------------
__global__ void to_half(const float* __restrict__ src,
                        __half* __restrict__ dst, int n)
{
    int i = blockIdx.x * blockDim.x + threadIdx.x;
    int stride = gridDim.x * blockDim.x;
    for (; i < n; i += stride) dst[i] = __float2half(src[i]);
}

// ---------------------------------------------------------------------------
// Kernel 1: x_proj SGEMM (unchanged, ~123us)
// ---------------------------------------------------------------------------
template <bool GATHER>
__global__ __launch_bounds__(256, 2)
void gemm_nt(const float* __restrict__ A, const float* __restrict__ Bmat,
             const float* __restrict__ bias, float* __restrict__ C,
             const int* __restrict__ idx, int M, int N, int K)
{
    __shared__ float As[2][8][128];
    __shared__ float Bs[2][8][128];

    const int tid  = threadIdx.x;
    const int mblk = blockIdx.y * 128;
    const int nblk = blockIdx.x * 128;

    const int arow = tid >> 1;
    const int kq   = (tid & 1) * 4;

    const float* Aptr;
    if (GATHER) Aptr = A + (size_t)idx[mblk + arow] * K;
    else        Aptr = A + (size_t)(mblk + arow) * K;
    const float* Bptr = Bmat + (size_t)(nblk + arow) * K;

    const int ty = tid >> 4;
    const int tx = tid & 15;

    unsigned long long acc2[8][4];
    #pragma unroll
    for (int i = 0; i < 8; i++)
        #pragma unroll
        for (int p = 0; p < 4; p++) acc2[i][p] = 0ull;

    {
        float4 a4 = *(const float4*)(Aptr + kq);
        float4 b4 = *(const float4*)(Bptr + kq);
        #pragma unroll
        for (int i = 0; i < 4; i++) {
            As[0][kq + i][arow] = ((const float*)&a4)[i];
            Bs[0][kq + i][arow] = ((const float*)&b4)[i];
        }
    }
    __syncthreads();

    const int nkt = K >> 3;
    for (int kt = 0; kt < nkt; kt++) {
        const int cur = kt & 1, nxt = cur ^ 1;
        float4 a4n, b4n;
        const bool more = (kt + 1 < nkt);
        if (more) {
            a4n = *(const float4*)(Aptr + (kt + 1) * 8 + kq);
            b4n = *(const float4*)(Bptr + (kt + 1) * 8 + kq);
        }
        #pragma unroll
        for (int k = 0; k < 8; k++) {
            float af[8];
            *(float4*)&af[0] = *(const float4*)&As[cur][k][ty * 8];
            *(float4*)&af[4] = *(const float4*)&As[cur][k][ty * 8 + 4];
            unsigned long long bp[4];
            const unsigned long long* bq =
                (const unsigned long long*)&Bs[cur][k][tx * 8];
            #pragma unroll
            for (int p = 0; p < 4; p++) bp[p] = bq[p];
            #pragma unroll
            for (int i = 0; i < 8; i++) {
                unsigned long long ad = pack2(af[i], af[i]);
                #pragma unroll
                for (int p = 0; p < 4; p++) ffma2(acc2[i][p], ad, bp[p]);
            }
        }
        if (more) {
            #pragma unroll
            for (int i = 0; i < 4; i++) {
                As[nxt][kq + i][arow] = ((const float*)&a4n)[i];
                Bs[nxt][kq + i][arow] = ((const float*)&b4n)[i];
            }
        }
        __syncthreads();
    }

    float bv[8];
    #pragma unroll
    for (int j = 0; j < 8; j++) bv[j] = bias[nblk + tx * 8 + j];

    #pragma unroll
    for (int i = 0; i < 8; i++) {
        size_t row = (size_t)(mblk + ty * 8 + i);
        float* cp = C + row * (size_t)N + nblk + tx * 8;
        float v[8];
        #pragma unroll
        for (int p = 0; p < 4; p++) {
            float lo, hi;
            unpack2(acc2[i][p], lo, hi);
            v[2 * p]     = lo + bv[2 * p];
            v[2 * p + 1] = hi + bv[2 * p + 1];
        }
        *(float4*)cp       = make_float4(v[0], v[1], v[2], v[3]);
        *(float4*)(cp + 4) = make_float4(v[4], v[5], v[6], v[7]);
    }
}

// ---------------------------------------------------------------------------
// Kernel 2: RNN scan (emits hseq as fp16 hi/lo)
// ---------------------------------------------------------------------------
__global__ __launch_bounds__(512, 1) __cluster_dims__(8, 1, 1)
void rnn_scan(const float* __restrict__ xproj,
              const float* __restrict__ hidden0,
              const float* __restrict__ W_hh,
              const float* __restrict__ b_hh,
              __half* __restrict__ hs_hi,
              __half* __restrict__ hs_lo,
              float* __restrict__ hfinal)
{
    __shared__ float h_buf[2][H_];
    __shared__ float part[8][64];

    const int tid   = threadIdx.x;
    const int batch = blockIdx.x >> 3;
    const int rank  = blockIdx.x & 7;
    const int out   = tid & 63;
    const int kc    = tid >> 6;
    const int kbase = kc * 64;
    const int grow  = rank * 64 + out;

    unsigned long long w2[32];
    {
        const unsigned long long* wq =
            (const unsigned long long*)(W_hh + (size_t)grow * H_ + kbase);
        #pragma unroll
        for (int j = 0; j < 32; j++) w2[j] = wq[j];
    }

    h_buf[0][tid] = hidden0[batch * H_ + tid];
    const float bhh = (tid < 64) ? b_hh[rank * 64 + tid] : 0.f;
    __syncthreads();

    const float* xp_b = xproj + (size_t)batch * S_ * H_ + rank * 64;
    __half* hh_b = hs_hi + (size_t)batch * S_ * H_ + rank * 64;
    __half* hl_b = hs_lo + (size_t)batch * S_ * H_ + rank * 64;

    float hn = 0.f;
    for (int t = 0; t < S_; t++) {
        const int pb = t & 1;

        float xp = 0.f;
        if (tid < 64) xp = xp_b[(size_t)t * H_ + tid];

        unsigned long long acc2 = 0ull;
        const unsigned long long* hq =
            (const unsigned long long*)&h_buf[pb][kbase];
        #pragma unroll
        for (int j = 0; j < 32; j++) ffma2(acc2, w2[j], hq[j]);
        float lo, hi; unpack2(acc2, lo, hi);
        part[kc][out] = lo + hi;
        __syncthreads();

        if (tid < 64) {
            float s = xp + bhh;
            #pragma unroll
            for (int c = 0; c < 8; c++) s += part[c][tid];
            hn = tanhf(s);
            __half hh = __float2half(hn);
            hh_b[(size_t)t * H_ + tid] = hh;
            hl_b[(size_t)t * H_ + tid] =
                __float2half(hn - __half2float(hh));

            uint32_t laddr = smem_u32(&h_buf[pb ^ 1][rank * 64 + tid]);
            #pragma unroll
            for (int pr = 0; pr < 8; pr++) {
                uint32_t paddr;
                asm("mapa.shared::cluster.u32 %0, %1, %2;"
                    : "=r"(paddr) : "r"(laddr), "r"(pr));
                asm volatile("st.shared::cluster.f32 [%0], %1;"
                             :: "r"(paddr), "f"(hn) : "memory");
            }
        }
        asm volatile("barrier.cluster.arrive.aligned;" ::: "memory");
        asm volatile("barrier.cluster.wait.aligned;"   ::: "memory");
    }

    if (tid < 64) hfinal[batch * H_ + rank * 64 + tid] = hn;
}

// ---------------------------------------------------------------------------
// Kernel 3: logits GEMM via mma.sync fp16.
// C = hseq @ W_out^T + b_out ;  D = Ahi*B + Alo*B  (A exact, B fp16)
// 128x128 CTA tile, 8 warps (4M x 2N), K-chunk 64, 2-stage cp.async pipeline,
// 3 operand tiles/stage (Ahi, Alo, B) of 18432B each -> 110.6KB smem,
// 2 CTAs/SM via __launch_bounds__(256, 2).
// ---------------------------------------------------------------------------
#define OP_PITCH  144                       // bytes per smem row (64 fp16 + pad)
#define OP_SZ     (128 * OP_PITCH)          // 18432 B per operand tile
#define STAGE_SZ  (3 * OP_SZ)               // Ahi, Alo, B
#define LOGITS_SMEM (2 * STAGE_SZ)          // 110592 B

__global__ __launch_bounds__(256, 2)
void logits_mma(const __half* __restrict__ Ahi,
                const __half* __restrict__ Alo,
                const __half* __restrict__ Bw,
                const float* __restrict__ bias,
                float* __restrict__ C)
{
    extern __shared__ char dsm[];
    const uint32_t sbase = smem_u32(dsm);

    const int tid  = threadIdx.x;
    const int warp = tid >> 5, lane = tid & 31;
    const int wm = warp & 3;                 // 0..3  (M)
    const int wn = warp >> 2;                // 0..1  (N)
    const int mblk = blockIdx.y * 128;
    const int nblk = blockIdx.x * 128;

    const char* opg[3] = { (const char*)Ahi, (const char*)Alo, (const char*)Bw };
    const int   r0op[3] = { mblk, mblk, nblk };

    // per-thread load: 4 x 16B chunks per operand per stage
    auto load_stage = [&](int kc, int st) {
        const uint32_t sst = sbase + (uint32_t)st * STAGE_SZ;
        #pragma unroll
        for (int op = 0; op < 3; op++) {
            #pragma unroll
            for (int j = 0; j < 4; j++) {
                int u = tid + 256 * j;
                int row = u >> 3, cc = u & 7;
                const void* g = opg[op] +
                    (size_t)(r0op[op] + row) * (H_ * 2) + kc * 128 + cc * 16;
                uint32_t s = sst + (uint32_t)op * OP_SZ + row * OP_PITCH + cc * 16;
                cp_async16(s, g);
            }
        }
        CP_COMMIT();
    };

    float acc[2][8][4];
    #pragma unroll
    for (int mi = 0; mi < 2; mi++)
        #pragma unroll
        for (int ni = 0; ni < 8; ni++)
            #pragma unroll
            for (int q = 0; q < 4; q++) acc[mi][ni][q] = 0.f;

    load_stage(0, 0);
    load_stage(1, 1);

    // ldmatrix address components (bytes within operand tile)
    const int arow  = wm * 32 + (lane & 15);          // + mi*16
    const int aoff  = (lane >> 4) * 16;
    const int nrow  = wn * 64 + (lane & 7) + ((lane >> 4) & 1) * 8;  // + g*16
    const int boff  = ((lane >> 3) & 1) * 16;

    #pragma unroll 1
    for (int kc = 0; kc < 8; kc++) {
        const int st = kc & 1;
        if (kc < 7) cp_wait<1>(); else cp_wait<0>();
        __syncthreads();

        const uint32_t sst = sbase + (uint32_t)st * STAGE_SZ;
        const uint32_t ahb = sst;
        const uint32_t alb = sst + OP_SZ;
        const uint32_t bwb = sst + 2 * OP_SZ;

        #pragma unroll
        for (int ks = 0; ks < 4; ks++) {
            const int kb = ks * 32;   // bytes (16 fp16)
            uint32_t ah[2][4], al[2][4];
            #pragma unroll
            for (int mi = 0; mi < 2; mi++) {
                ldsm4(ahb + (arow + mi * 16) * OP_PITCH + kb + aoff,
                      ah[mi][0], ah[mi][1], ah[mi][2], ah[mi][3]);
                ldsm4(alb + (arow + mi * 16) * OP_PITCH + kb + aoff,
                      al[mi][0], al[mi][1], al[mi][2], al[mi][3]);
            }
            #pragma unroll
            for (int g = 0; g < 4; g++) {
                uint32_t bh[4];
                ldsm4(bwb + (nrow + g * 16) * OP_PITCH + kb + boff,
                      bh[0], bh[1], bh[2], bh[3]);
                #pragma unroll
                for (int mi = 0; mi < 2; mi++) {
                    float* d0 = acc[mi][2 * g];
                    float* d1 = acc[mi][2 * g + 1];
                    mma_f16(d0, ah[mi][0], ah[mi][1], ah[mi][2], ah[mi][3],
                            bh[0], bh[1]);
                    mma_f16(d0, al[mi][0], al[mi][1], al[mi][2], al[mi][3],
                            bh[0], bh[1]);
                    mma_f16(d1, ah[mi][0], ah[mi][1], ah[mi][2], ah[mi][3],
                            bh[2], bh[3]);
                    mma_f16(d1, al[mi][0], al[mi][1], al[mi][2], al[mi][3],
                            bh[2], bh[3]);
                }
            }
        }
        __syncthreads();
        if (kc + 2 < 8) load_stage(kc + 2, st);
    }

    // epilogue
    const int rg = mblk + wm * 32 + (lane >> 2);
    const int cg = nblk + wn * 64 + (lane & 3) * 2;
    #pragma unroll
    for (int mi = 0; mi < 2; mi++) {
        #pragma unroll
        for (int ni = 0; ni < 8; ni++) {
            const int row = rg + mi * 16;
            const int col = cg + ni * 8;
            const float b0 = __ldg(bias + col);
            const float b1 = __ldg(bias + col + 1);
            float2 v0 = make_float2(acc[mi][ni][0] + b0, acc[mi][ni][1] + b1);
            float2 v1 = make_float2(acc[mi][ni][2] + b0, acc[mi][ni][3] + b1);
            *(float2*)(C + (size_t)row * V_ + col)       = v0;
            *(float2*)(C + (size_t)(row + 8) * V_ + col) = v1;
        }
    }
}

// ---------------------------------------------------------------------------
// Launch
// inputs: 0=x(i32)[B,S] 1=hidden[B,H] 2=embedding[V,E] 3=W_ih[H,E]
//         4=W_hh[H,H] 5=b_ih[H] 6=b_hh[H] 7=W_out[V,H] 8=b_out[V]
// output: logits [B,S,V] then h_final [B,H]
// ---------------------------------------------------------------------------
extern "C" void kernel_launch(void* const* d_in, const int* in_sizes, int n_in,
                              void* d_out, int out_size)
{
    const int*   x         = (const int*)  d_in[0];
    const float* hidden    = (const float*)d_in[1];
    const float* embedding = (const float*)d_in[2];
    const float* W_ih      = (const float*)d_in[3];
    const float* W_hh      = (const float*)d_in[4];
    const float* b_ih      = (const float*)d_in[5];
    const float* b_hh      = (const float*)d_in[6];
    const float* W_out     = (const float*)d_in[7];
    const float* b_out     = (const float*)d_in[8];
    float* out = (float*)d_out;

    float *xproj, *dummy;
    __half *hhi, *hlo, *w16;
    cudaGetSymbolAddress((void**)&xproj, g_xproj);
    cudaGetSymbolAddress((void**)&hhi,   g_hhi);
    cudaGetSymbolAddress((void**)&hlo,   g_hlo);
    cudaGetSymbolAddress((void**)&w16,   g_w16);
    cudaGetSymbolAddress((void**)&dummy, g_dummy_hf);

    float* hfin = ((long long)out_size >= VOUT + (long long)B_ * H_)
                      ? (out + VOUT) : dummy;

    static bool attr_done = false;
    if (!attr_done) {
        cudaFuncSetAttribute(logits_mma,
                             cudaFuncAttributeMaxDynamicSharedMemorySize,
                             LOGITS_SMEM);
        attr_done = true;
    }

    // 0) W_out -> fp16
    to_half<<<2048, 256>>>(W_out, w16, V_ * H_);

    // 1) x_proj = emb[x] @ W_ih^T + b_ih     [16384,512]
    gemm_nt<true><<<dim3(H_ / 128, MTOT / 128), 256>>>(
        embedding, W_ih, b_ih, xproj, x, MTOT, H_, E_);

    // 2) sequential scan -> hseq (fp16 hi/lo), h_final
    rnn_scan<<<64, 512>>>(xproj, hidden, W_hh, b_hh, hhi, hlo, hfin);

    // 3) logits = hseq @ W_out^T + b_out    [16384,16000] via mma.sync
    logits_mma<<<dim3(V_ / 128, MTOT / 128), 256, LOGITS_SMEM>>>(
        hhi, hlo, w16, b_out, out);
}

// round 7
// speedup vs baseline: 2.8676x; 1.2301x over previous
#include <cuda_runtime.h>
#include <cuda_fp16.h>
#include <cstdint>

// ---------------------------------------------------------------------------
// SimpleRNN: logits = W_out( scan_tanh( W_ih·emb[x] + b_ih , W_hh, b_hh ) ) + b_out
// B=8, S=2048, E=256, H=512, V=16000
// Round 6: logits GEMM single-term fp16 mma.sync (A=hseq fp16, B=W_out fp16,
// fp32 accumulate). Error ~= sqrt(2) * R6's 2.05e-4 ~ 2.9e-4, margin ~3.4x.
// 3-stage cp.async pipeline, 2 CTAs/SM (110.6KB smem, 128 regs).
// ---------------------------------------------------------------------------

#define B_  8
#define S_  2048
#define E_  256
#define H_  512
#define V_  16000
#define MTOT (B_ * S_)                      // 16384
static const long long VOUT = (long long)B_ * S_ * V_;   // 262,144,000

// Scratch (device globals: no allocation allowed)
__device__ float  g_xproj[(size_t)MTOT * H_];    // 33.5 MB
__device__ __half g_h16  [(size_t)MTOT * H_];    // 16.8 MB
__device__ __half g_w16  [(size_t)V_  * H_];     // 16.4 MB
__device__ float  g_dummy_hf[B_ * H_];

// ---------------- small PTX helpers -----------------------------------------
__device__ __forceinline__ void ffma2(unsigned long long& acc,
                                      unsigned long long a,
                                      unsigned long long b) {
    asm("fma.rn.f32x2 %0, %1, %2, %0;" : "+l"(acc) : "l"(a), "l"(b));
}
__device__ __forceinline__ unsigned long long pack2(float x, float y) {
    unsigned long long r;
    asm("mov.b64 %0, {%1, %2};" : "=l"(r) : "f"(x), "f"(y));
    return r;
}
__device__ __forceinline__ void unpack2(unsigned long long v, float& lo, float& hi) {
    asm("mov.b64 {%0, %1}, %2;" : "=f"(lo), "=f"(hi) : "l"(v));
}
__device__ __forceinline__ uint32_t smem_u32(const void* p) {
    uint32_t a;
    asm("{ .reg .u64 t; cvta.to.shared.u64 t, %1; cvt.u32.u64 %0, t; }"
        : "=r"(a) : "l"(p));
    return a;
}
__device__ __forceinline__ void cp_async16(uint32_t saddr, const void* gaddr) {
    asm volatile("cp.async.cg.shared.global [%0], [%1], 16;"
                 :: "r"(saddr), "l"(gaddr));
}
#define CP_COMMIT() asm volatile("cp.async.commit_group;" ::: "memory")
template <int N>
__device__ __forceinline__ void cp_wait() {
    asm volatile("cp.async.wait_group %0;" :: "n"(N) : "memory");
}
__device__ __forceinline__ void ldsm4(uint32_t addr, uint32_t& r0, uint32_t& r1,
                                      uint32_t& r2, uint32_t& r3) {
    asm volatile("ldmatrix.sync.aligned.m8n8.x4.shared.b16 {%0,%1,%2,%3}, [%4];"
                 : "=r"(r0), "=r"(r1), "=r"(r2), "=r"(r3) : "r"(addr));
}
__device__ __forceinline__ void mma_f16(float* d,
                                        uint32_t a0, uint32_t a1,
                                        uint32_t a2, uint32_t a3,
                                        uint32_t b0, uint32_t b1) {
    asm volatile("mma.sync.aligned.m16n8k16.row.col.f32.f16.f16.f32 "
                 "{%0,%1,%2,%3}, {%4,%5,%6,%7}, {%8,%9}, {%0,%1,%2,%3};"
                 : "+f"(d[0]), "+f"(d[1]), "+f"(d[2]), "+f"(d[3])
                 : "r"(a0), "r"(a1), "r"(a2), "r"(a3), "r"(b0), "r"(b1));
}

// ---------------------------------------------------------------------------
// Kernel 0: W_out fp32 -> fp16
// ---------------------------------------------------------------------------
__global__ void to_half(const float* __restrict__ src,
                        __half* __restrict__ dst, int n)
{
    int i = blockIdx.x * blockDim.x + threadIdx.x;
    int stride = gridDim.x * blockDim.x;
    for (; i < n; i += stride) dst[i] = __float2half(src[i]);
}

// ---------------------------------------------------------------------------
// Kernel 1: x_proj SGEMM (unchanged, ~123us)
// ---------------------------------------------------------------------------
template <bool GATHER>
__global__ __launch_bounds__(256, 2)
void gemm_nt(const float* __restrict__ A, const float* __restrict__ Bmat,
             const float* __restrict__ bias, float* __restrict__ C,
             const int* __restrict__ idx, int M, int N, int K)
{
    __shared__ float As[2][8][128];
    __shared__ float Bs[2][8][128];

    const int tid  = threadIdx.x;
    const int mblk = blockIdx.y * 128;
    const int nblk = blockIdx.x * 128;

    const int arow = tid >> 1;
    const int kq   = (tid & 1) * 4;

    const float* Aptr;
    if (GATHER) Aptr = A + (size_t)idx[mblk + arow] * K;
    else        Aptr = A + (size_t)(mblk + arow) * K;
    const float* Bptr = Bmat + (size_t)(nblk + arow) * K;

    const int ty = tid >> 4;
    const int tx = tid & 15;

    unsigned long long acc2[8][4];
    #pragma unroll
    for (int i = 0; i < 8; i++)
        #pragma unroll
        for (int p = 0; p < 4; p++) acc2[i][p] = 0ull;

    {
        float4 a4 = *(const float4*)(Aptr + kq);
        float4 b4 = *(const float4*)(Bptr + kq);
        #pragma unroll
        for (int i = 0; i < 4; i++) {
            As[0][kq + i][arow] = ((const float*)&a4)[i];
            Bs[0][kq + i][arow] = ((const float*)&b4)[i];
        }
    }
    __syncthreads();

    const int nkt = K >> 3;
    for (int kt = 0; kt < nkt; kt++) {
        const int cur = kt & 1, nxt = cur ^ 1;
        float4 a4n, b4n;
        const bool more = (kt + 1 < nkt);
        if (more) {
            a4n = *(const float4*)(Aptr + (kt + 1) * 8 + kq);
            b4n = *(const float4*)(Bptr + (kt + 1) * 8 + kq);
        }
        #pragma unroll
        for (int k = 0; k < 8; k++) {
            float af[8];
            *(float4*)&af[0] = *(const float4*)&As[cur][k][ty * 8];
            *(float4*)&af[4] = *(const float4*)&As[cur][k][ty * 8 + 4];
            unsigned long long bp[4];
            const unsigned long long* bq =
                (const unsigned long long*)&Bs[cur][k][tx * 8];
            #pragma unroll
            for (int p = 0; p < 4; p++) bp[p] = bq[p];
            #pragma unroll
            for (int i = 0; i < 8; i++) {
                unsigned long long ad = pack2(af[i], af[i]);
                #pragma unroll
                for (int p = 0; p < 4; p++) ffma2(acc2[i][p], ad, bp[p]);
            }
        }
        if (more) {
            #pragma unroll
            for (int i = 0; i < 4; i++) {
                As[nxt][kq + i][arow] = ((const float*)&a4n)[i];
                Bs[nxt][kq + i][arow] = ((const float*)&b4n)[i];
            }
        }
        __syncthreads();
    }

    float bv[8];
    #pragma unroll
    for (int j = 0; j < 8; j++) bv[j] = bias[nblk + tx * 8 + j];

    #pragma unroll
    for (int i = 0; i < 8; i++) {
        size_t row = (size_t)(mblk + ty * 8 + i);
        float* cp = C + row * (size_t)N + nblk + tx * 8;
        float v[8];
        #pragma unroll
        for (int p = 0; p < 4; p++) {
            float lo, hi;
            unpack2(acc2[i][p], lo, hi);
            v[2 * p]     = lo + bv[2 * p];
            v[2 * p + 1] = hi + bv[2 * p + 1];
        }
        *(float4*)cp       = make_float4(v[0], v[1], v[2], v[3]);
        *(float4*)(cp + 4) = make_float4(v[4], v[5], v[6], v[7]);
    }
}

// ---------------------------------------------------------------------------
// Kernel 2: RNN scan (emits hseq as single fp16)
// ---------------------------------------------------------------------------
__global__ __launch_bounds__(512, 1) __cluster_dims__(8, 1, 1)
void rnn_scan(const float* __restrict__ xproj,
              const float* __restrict__ hidden0,
              const float* __restrict__ W_hh,
              const float* __restrict__ b_hh,
              __half* __restrict__ hs16,
              float* __restrict__ hfinal)
{
    __shared__ float h_buf[2][H_];
    __shared__ float part[8][64];

    const int tid   = threadIdx.x;
    const int batch = blockIdx.x >> 3;
    const int rank  = blockIdx.x & 7;
    const int out   = tid & 63;
    const int kc    = tid >> 6;
    const int kbase = kc * 64;
    const int grow  = rank * 64 + out;

    unsigned long long w2[32];
    {
        const unsigned long long* wq =
            (const unsigned long long*)(W_hh + (size_t)grow * H_ + kbase);
        #pragma unroll
        for (int j = 0; j < 32; j++) w2[j] = wq[j];
    }

    h_buf[0][tid] = hidden0[batch * H_ + tid];
    const float bhh = (tid < 64) ? b_hh[rank * 64 + tid] : 0.f;
    __syncthreads();

    const float* xp_b = xproj + (size_t)batch * S_ * H_ + rank * 64;
    __half* hh_b = hs16 + (size_t)batch * S_ * H_ + rank * 64;

    float hn = 0.f;
    for (int t = 0; t < S_; t++) {
        const int pb = t & 1;

        float xp = 0.f;
        if (tid < 64) xp = xp_b[(size_t)t * H_ + tid];

        unsigned long long acc2 = 0ull;
        const unsigned long long* hq =
            (const unsigned long long*)&h_buf[pb][kbase];
        #pragma unroll
        for (int j = 0; j < 32; j++) ffma2(acc2, w2[j], hq[j]);
        float lo, hi; unpack2(acc2, lo, hi);
        part[kc][out] = lo + hi;
        __syncthreads();

        if (tid < 64) {
            float s = xp + bhh;
            #pragma unroll
            for (int c = 0; c < 8; c++) s += part[c][tid];
            hn = tanhf(s);
            hh_b[(size_t)t * H_ + tid] = __float2half(hn);

            uint32_t laddr = smem_u32(&h_buf[pb ^ 1][rank * 64 + tid]);
            #pragma unroll
            for (int pr = 0; pr < 8; pr++) {
                uint32_t paddr;
                asm("mapa.shared::cluster.u32 %0, %1, %2;"
                    : "=r"(paddr) : "r"(laddr), "r"(pr));
                asm volatile("st.shared::cluster.f32 [%0], %1;"
                             :: "r"(paddr), "f"(hn) : "memory");
            }
        }
        asm volatile("barrier.cluster.arrive.aligned;" ::: "memory");
        asm volatile("barrier.cluster.wait.aligned;"   ::: "memory");
    }

    if (tid < 64) hfinal[batch * H_ + rank * 64 + tid] = hn;
}

// ---------------------------------------------------------------------------
// Kernel 3: logits GEMM via mma.sync fp16, single term D = A*B.
// 128x128 CTA tile, 8 warps (4M x 2N), K-chunk 64, 3-stage cp.async pipeline,
// 2 operand tiles/stage (A, B) of 18432B -> 110.6KB smem, 2 CTAs/SM.
// ---------------------------------------------------------------------------
#define OP_PITCH  144                       // bytes per smem row (64 fp16 + pad)
#define OP_SZ     (128 * OP_PITCH)          // 18432 B per operand tile
#define STAGE_SZ  (2 * OP_SZ)               // A, B
#define NSTAGE    3
#define LOGITS_SMEM (NSTAGE * STAGE_SZ)     // 110592 B

__global__ __launch_bounds__(256, 2)
void logits_mma(const __half* __restrict__ Ah,
                const __half* __restrict__ Bw,
                const float* __restrict__ bias,
                float* __restrict__ C)
{
    extern __shared__ char dsm[];
    const uint32_t sbase = smem_u32(dsm);

    const int tid  = threadIdx.x;
    const int warp = tid >> 5, lane = tid & 31;
    const int wm = warp & 3;                 // 0..3  (M)
    const int wn = warp >> 2;                // 0..1  (N)
    const int mblk = blockIdx.y * 128;
    const int nblk = blockIdx.x * 128;

    const char* opg[2] = { (const char*)Ah, (const char*)Bw };
    const int   r0op[2] = { mblk, nblk };

    // per-thread load: 4 x 16B chunks per operand per stage
    auto load_stage = [&](int kc, int st) {
        const uint32_t sst = sbase + (uint32_t)st * STAGE_SZ;
        #pragma unroll
        for (int op = 0; op < 2; op++) {
            #pragma unroll
            for (int j = 0; j < 4; j++) {
                int u = tid + 256 * j;
                int row = u >> 3, cc = u & 7;
                const void* g = opg[op] +
                    (size_t)(r0op[op] + row) * (H_ * 2) + kc * 128 + cc * 16;
                uint32_t s = sst + (uint32_t)op * OP_SZ + row * OP_PITCH + cc * 16;
                cp_async16(s, g);
            }
        }
        CP_COMMIT();
    };

    float acc[2][8][4];
    #pragma unroll
    for (int mi = 0; mi < 2; mi++)
        #pragma unroll
        for (int ni = 0; ni < 8; ni++)
            #pragma unroll
            for (int q = 0; q < 4; q++) acc[mi][ni][q] = 0.f;

    load_stage(0, 0);
    load_stage(1, 1);
    load_stage(2, 2);

    // ldmatrix address components (bytes within operand tile)
    const int arow  = wm * 32 + (lane & 15);          // + mi*16
    const int aoff  = (lane >> 4) * 16;
    const int nrow  = wn * 64 + (lane & 7) + ((lane >> 4) & 1) * 8;  // + g*16
    const int boff  = ((lane >> 3) & 1) * 16;

    #pragma unroll 1
    for (int kc = 0; kc < 8; kc++) {
        const int st = kc - (kc / NSTAGE) * NSTAGE;   // kc % 3
        cp_wait<NSTAGE - 1>();
        __syncthreads();

        const uint32_t sst = sbase + (uint32_t)st * STAGE_SZ;
        const uint32_t ahb = sst;
        const uint32_t bwb = sst + OP_SZ;

        #pragma unroll
        for (int ks = 0; ks < 4; ks++) {
            const int kb = ks * 32;   // bytes (16 fp16)
            uint32_t ah[2][4];
            #pragma unroll
            for (int mi = 0; mi < 2; mi++)
                ldsm4(ahb + (arow + mi * 16) * OP_PITCH + kb + aoff,
                      ah[mi][0], ah[mi][1], ah[mi][2], ah[mi][3]);
            #pragma unroll
            for (int g = 0; g < 4; g++) {
                uint32_t bh[4];
                ldsm4(bwb + (nrow + g * 16) * OP_PITCH + kb + boff,
                      bh[0], bh[1], bh[2], bh[3]);
                #pragma unroll
                for (int mi = 0; mi < 2; mi++) {
                    mma_f16(acc[mi][2 * g],
                            ah[mi][0], ah[mi][1], ah[mi][2], ah[mi][3],
                            bh[0], bh[1]);
                    mma_f16(acc[mi][2 * g + 1],
                            ah[mi][0], ah[mi][1], ah[mi][2], ah[mi][3],
                            bh[2], bh[3]);
                }
            }
        }
        __syncthreads();
        if (kc + NSTAGE < 8) {
            load_stage(kc + NSTAGE, st);
        } else {
            CP_COMMIT();          // empty group keeps wait_group accounting
        }
    }

    // epilogue
    const int rg = mblk + wm * 32 + (lane >> 2);
    const int cg = nblk + wn * 64 + (lane & 3) * 2;
    #pragma unroll
    for (int mi = 0; mi < 2; mi++) {
        #pragma unroll
        for (int ni = 0; ni < 8; ni++) {
            const int row = rg + mi * 16;
            const int col = cg + ni * 8;
            const float b0 = __ldg(bias + col);
            const float b1 = __ldg(bias + col + 1);
            float2 v0 = make_float2(acc[mi][ni][0] + b0, acc[mi][ni][1] + b1);
            float2 v1 = make_float2(acc[mi][ni][2] + b0, acc[mi][ni][3] + b1);
            *(float2*)(C + (size_t)row * V_ + col)       = v0;
            *(float2*)(C + (size_t)(row + 8) * V_ + col) = v1;
        }
    }
}

// ---------------------------------------------------------------------------
// Launch
// inputs: 0=x(i32)[B,S] 1=hidden[B,H] 2=embedding[V,E] 3=W_ih[H,E]
//         4=W_hh[H,H] 5=b_ih[H] 6=b_hh[H] 7=W_out[V,H] 8=b_out[V]
// output: logits [B,S,V] then h_final [B,H]
// ---------------------------------------------------------------------------
extern "C" void kernel_launch(void* const* d_in, const int* in_sizes, int n_in,
                              void* d_out, int out_size)
{
    const int*   x         = (const int*)  d_in[0];
    const float* hidden    = (const float*)d_in[1];
    const float* embedding = (const float*)d_in[2];
    const float* W_ih      = (const float*)d_in[3];
    const float* W_hh      = (const float*)d_in[4];
    const float* b_ih      = (const float*)d_in[5];
    const float* b_hh      = (const float*)d_in[6];
    const float* W_out     = (const float*)d_in[7];
    const float* b_out     = (const float*)d_in[8];
    float* out = (float*)d_out;

    float *xproj, *dummy;
    __half *h16, *w16;
    cudaGetSymbolAddress((void**)&xproj, g_xproj);
    cudaGetSymbolAddress((void**)&h16,   g_h16);
    cudaGetSymbolAddress((void**)&w16,   g_w16);
    cudaGetSymbolAddress((void**)&dummy, g_dummy_hf);

    float* hfin = ((long long)out_size >= VOUT + (long long)B_ * H_)
                      ? (out + VOUT) : dummy;

    static bool attr_done = false;
    if (!attr_done) {
        cudaFuncSetAttribute(logits_mma,
                             cudaFuncAttributeMaxDynamicSharedMemorySize,
                             LOGITS_SMEM);
        attr_done = true;
    }

    // 0) W_out -> fp16
    to_half<<<2048, 256>>>(W_out, w16, V_ * H_);

    // 1) x_proj = emb[x] @ W_ih^T + b_ih     [16384,512]
    gemm_nt<true><<<dim3(H_ / 128, MTOT / 128), 256>>>(
        embedding, W_ih, b_ih, xproj, x, MTOT, H_, E_);

    // 2) sequential scan -> hseq (fp16), h_final
    rnn_scan<<<64, 512>>>(xproj, hidden, W_hh, b_hh, h16, hfin);

    // 3) logits = hseq @ W_out^T + b_out    [16384,16000] via mma.sync
    logits_mma<<<dim3(V_ / 128, MTOT / 128), 256, LOGITS_SMEM>>>(
        h16, w16, b_out, out);
}